// round 3
// baseline (speedup 1.0000x reference)
#include <cuda_runtime.h>
#include <cstdint>

#define B_TOTAL 65536
#define TLEN 200
#define DIN 6
#define HID 50
#define NSTEP 101

// Scratch for pooled initial state (static __device__ global: allocation-free).
__device__ float g_y0[B_TOTAL * DIN];

// ---------------- f32x2 helpers (FFMA2 only reachable via PTX) ----------------
__device__ __forceinline__ unsigned long long pack_dup(float v) {
    unsigned long long r;
    asm("mov.b64 %0, {%1, %2};" : "=l"(r) : "f"(v), "f"(v));
    return r;
}
__device__ __forceinline__ unsigned long long pack2f(float a, float b) {
    unsigned long long r;
    asm("mov.b64 %0, {%1, %2};" : "=l"(r) : "f"(a), "f"(b));
    return r;
}
__device__ __forceinline__ void unpack2(unsigned long long v, float& lo, float& hi) {
    asm("mov.b64 {%0, %1}, %2;" : "=f"(lo), "=f"(hi) : "l"(v));
}
__device__ __forceinline__ unsigned long long ffma2(unsigned long long a,
                                                    unsigned long long b,
                                                    unsigned long long c) {
    unsigned long long d;
    asm("fma.rn.f32x2 %0, %1, %2, %3;" : "=l"(d) : "l"(a), "l"(b), "l"(c));
    return d;
}
__device__ __forceinline__ unsigned smem_addr(const void* p) {
    return (unsigned)__cvta_generic_to_shared(p);
}
__device__ __forceinline__ void lds2(unsigned a, unsigned long long& x, unsigned long long& y) {
    asm("ld.shared.v2.u64 {%0, %1}, [%2];" : "=l"(x), "=l"(y) : "r"(a));
}
__device__ __forceinline__ unsigned long long lds1(unsigned a) {
    unsigned long long x;
    asm("ld.shared.u64 %0, [%1];" : "=l"(x) : "r"(a));
    return x;
}
__device__ __forceinline__ void sts1(unsigned a, unsigned long long v) {
    asm volatile("st.shared.u64 [%0], %1;" :: "r"(a), "l"(v));
}

struct SAddrs { unsigned w1, b1, w2, b2, w3, b3, h; };

// ---------------- MLP dynamics f(y): 6 -> 50 -> 50 -> 6, ReLU ----------------
// Weights in shared: W1 rows [6][52], W2 rows [50][52], W3 rows [50][8].
// h1 (post-ReLU) is parked in a per-thread private smem slab to keep the
// peak register live set ~= h2 only (fits 128 regs -> occ 4, zero spill).
__device__ __forceinline__ void mlp_f(const float* yt, float* k, const SAddrs s) {
    // ---- layer 1: h1 = ReLU(y @ W1 + b1), then park in smem ----
    {
        unsigned long long h1[25];
        unsigned a = s.b1;
        #pragma unroll
        for (int p = 0; p < 12; p++) lds2(a + 16 * p, h1[2 * p], h1[2 * p + 1]);
        h1[24] = lds1(a + 192);
        #pragma unroll
        for (int d = 0; d < DIN; d++) {
            unsigned long long yd = pack_dup(yt[d]);
            unsigned r = s.w1 + d * 208;
            #pragma unroll
            for (int p = 0; p < 12; p++) {
                unsigned long long w0, w1;
                lds2(r + 16 * p, w0, w1);
                h1[2 * p]     = ffma2(yd, w0, h1[2 * p]);
                h1[2 * p + 1] = ffma2(yd, w1, h1[2 * p + 1]);
            }
            h1[24] = ffma2(yd, lds1(r + 192), h1[24]);
        }
        #pragma unroll
        for (int q = 0; q < 25; q++) {
            float x, z;
            unpack2(h1[q], x, z);
            sts1(s.h + q * 1024u, pack2f(fmaxf(x, 0.0f), fmaxf(z, 0.0f)));
        }
    }

    // ---- layer 2: h2 = ReLU(h1 @ W2 + b2) (h2 in regs, h1 from smem) ----
    unsigned long long h2[25];
    {
        unsigned a = s.b2;
        #pragma unroll
        for (int p = 0; p < 12; p++) lds2(a + 16 * p, h2[2 * p], h2[2 * p + 1]);
        h2[24] = lds1(a + 192);
    }
    #pragma unroll 1
    for (int q = 0; q < 25; q++) {
        float a, b;
        unpack2(lds1(s.h + q * 1024u), a, b);
        unsigned long long da = pack_dup(a), db = pack_dup(b);
        unsigned r0 = s.w2 + (2 * q) * 208;
        unsigned r1 = r0 + 208;
        #pragma unroll
        for (int p = 0; p < 12; p++) {
            unsigned long long w0, w1;
            lds2(r0 + 16 * p, w0, w1);
            h2[2 * p]     = ffma2(da, w0, h2[2 * p]);
            h2[2 * p + 1] = ffma2(da, w1, h2[2 * p + 1]);
        }
        h2[24] = ffma2(da, lds1(r0 + 192), h2[24]);
        #pragma unroll
        for (int p = 0; p < 12; p++) {
            unsigned long long w0, w1;
            lds2(r1 + 16 * p, w0, w1);
            h2[2 * p]     = ffma2(db, w0, h2[2 * p]);
            h2[2 * p + 1] = ffma2(db, w1, h2[2 * p + 1]);
        }
        h2[24] = ffma2(db, lds1(r1 + 192), h2[24]);
    }

    // ---- layer 3: k = ReLU(h2) @ W3 + b3 ----
    unsigned long long o0, o1, o2;
    lds2(s.b3, o0, o1);
    o2 = lds1(s.b3 + 16);
    #pragma unroll 1
    for (int q = 0; q < 25; q++) {
        float a, b;
        unpack2(h2[q], a, b);
        a = fmaxf(a, 0.0f);
        b = fmaxf(b, 0.0f);
        unsigned long long da = pack_dup(a), db = pack_dup(b);
        unsigned r0 = s.w3 + (2 * q) * 32;
        unsigned long long w0, w1;
        lds2(r0, w0, w1);
        o0 = ffma2(da, w0, o0);
        o1 = ffma2(da, w1, o1);
        o2 = ffma2(da, lds1(r0 + 16), o2);
        lds2(r0 + 32, w0, w1);
        o0 = ffma2(db, w0, o0);
        o1 = ffma2(db, w1, o1);
        o2 = ffma2(db, lds1(r0 + 48), o2);
    }
    unpack2(o0, k[0], k[1]);
    unpack2(o1, k[2], k[3]);
    unpack2(o2, k[4], k[5]);
}

// ---------------- Phase A: y0 = mean over T (warp per sample) ----------------
// Lane l (<30) reads float2 at indices l + 30k: class (l%3) is lane-invariant,
// so accumulators stay in fixed registers; loads stay fully coalesced.
__global__ void mean_kernel(const float* __restrict__ x0) {
    const unsigned w = (blockIdx.x * blockDim.x + threadIdx.x) >> 5;
    const int lane = threadIdx.x & 31;
    if (w >= B_TOTAL) return;
    const float2* p = reinterpret_cast<const float2*>(x0) + (size_t)w * 600u;
    float sx = 0.0f, sy = 0.0f;
    if (lane < 30) {
        #pragma unroll
        for (int kk = 0; kk < 20; kk++) {
            float2 v = __ldg(p + lane + 30 * kk);
            sx += v.x;
            sy += v.y;
        }
    }
    const int c = lane % 3;
    float v0 = (c == 0) ? sx : 0.0f, v1 = (c == 0) ? sy : 0.0f;
    float v2 = (c == 1) ? sx : 0.0f, v3 = (c == 1) ? sy : 0.0f;
    float v4 = (c == 2) ? sx : 0.0f, v5 = (c == 2) ? sy : 0.0f;
    #pragma unroll
    for (int o = 16; o; o >>= 1) {
        v0 += __shfl_xor_sync(0xffffffffu, v0, o);
        v1 += __shfl_xor_sync(0xffffffffu, v1, o);
        v2 += __shfl_xor_sync(0xffffffffu, v2, o);
        v3 += __shfl_xor_sync(0xffffffffu, v3, o);
        v4 += __shfl_xor_sync(0xffffffffu, v4, o);
        v5 += __shfl_xor_sync(0xffffffffu, v5, o);
    }
    if (lane == 0) {
        const float inv = 1.0f / (float)TLEN;
        float* o = g_y0 + (size_t)w * 6u;
        o[0] = v0 * inv; o[1] = v1 * inv; o[2] = v2 * inv;
        o[3] = v3 * inv; o[4] = v4 * inv; o[5] = v5 * inv;
    }
}

// ---------------- Phase B: RK4 integration, one sample per thread ----------------
__global__ void __launch_bounds__(128, 4) ode_kernel(
    const float* __restrict__ t_span,
    const float* __restrict__ W1, const float* __restrict__ b1,
    const float* __restrict__ W2, const float* __restrict__ b2,
    const float* __restrict__ W3, const float* __restrict__ b3,
    float* __restrict__ out) {
    __shared__ __align__(16) float sW1[DIN * 52];
    __shared__ __align__(16) float sW2[HID * 52];
    __shared__ __align__(16) float sW3[HID * 8];
    __shared__ __align__(16) float sB1[52];
    __shared__ __align__(16) float sB2[52];
    __shared__ __align__(16) float sB3[8];
    __shared__ float sTs[NSTEP + 1];
    // Per-thread private h1 slab: slot [q*128 + tid], 25 u64 per thread.
    __shared__ __align__(16) unsigned long long sH[25 * 128];

    const int t = threadIdx.x;
    for (int i = t; i < DIN * HID; i += 128) sW1[(i / HID) * 52 + (i % HID)] = W1[i];
    for (int i = t; i < HID * HID; i += 128) sW2[(i / HID) * 52 + (i % HID)] = W2[i];
    for (int i = t; i < HID * DIN; i += 128) sW3[(i / DIN) * 8 + (i % DIN)] = W3[i];
    if (t < HID) { sB1[t] = b1[t]; sB2[t] = b2[t]; }
    if (t < DIN) sB3[t] = b3[t];
    if (t < NSTEP + 1) sTs[t] = t_span[t];
    __syncthreads();

    SAddrs s;
    s.w1 = smem_addr(sW1); s.b1 = smem_addr(sB1);
    s.w2 = smem_addr(sW2); s.b2 = smem_addr(sB2);
    s.w3 = smem_addr(sW3); s.b3 = smem_addr(sB3);
    s.h  = smem_addr(sH) + (unsigned)t * 8u;

    const int gid = blockIdx.x * 128 + t;
    float y[6];
    #pragma unroll
    for (int d = 0; d < 6; d++) y[d] = g_y0[gid * 6 + d];

    float yt[6], k[6], acc[6];

    #pragma unroll 1
    for (int stp = 0; stp < NSTEP; stp++) {
        const float dt = sTs[stp + 1] - sTs[stp];
        #pragma unroll
        for (int d = 0; d < 6; d++) yt[d] = y[d];
        #pragma unroll 1
        for (int st = 0; st < 4; st++) {
            mlp_f(yt, k, s);
            if (st == 0) {
                #pragma unroll
                for (int d = 0; d < 6; d++) { acc[d] = k[d]; yt[d] = fmaf(0.5f * dt, k[d], y[d]); }
            } else if (st == 1) {
                #pragma unroll
                for (int d = 0; d < 6; d++) { acc[d] += 2.0f * k[d]; yt[d] = fmaf(0.5f * dt, k[d], y[d]); }
            } else if (st == 2) {
                #pragma unroll
                for (int d = 0; d < 6; d++) { acc[d] += 2.0f * k[d]; yt[d] = fmaf(dt, k[d], y[d]); }
            } else {
                #pragma unroll
                for (int d = 0; d < 6; d++) y[d] = fmaf(dt * (1.0f / 6.0f), acc[d] + k[d], y[d]);
            }
        }
    }

    #pragma unroll
    for (int d = 0; d < 6; d++) out[gid * 6 + d] = y[d];
}

extern "C" void kernel_launch(void* const* d_in, const int* in_sizes, int n_in,
                              void* d_out, int out_size) {
    const float* x0 = (const float*)d_in[0];
    const float* ts = (const float*)d_in[1];
    const float* W1 = (const float*)d_in[2];
    const float* b1 = (const float*)d_in[3];
    const float* W2 = (const float*)d_in[4];
    const float* b2 = (const float*)d_in[5];
    const float* W3 = (const float*)d_in[6];
    const float* b3 = (const float*)d_in[7];
    float* out = (float*)d_out;

    mean_kernel<<<8192, 256>>>(x0);
    ode_kernel<<<512, 128>>>(ts, W1, b1, W2, b2, W3, b3, out);
}